// round 8
// baseline (speedup 1.0000x reference)
#include <cuda_runtime.h>
#include <cuda_fp16.h>
#include <cstdint>

#define B_    4
#define N1_   2048
#define N2_   8192
#define C1_   256
#define C2_   128
#define INCH  384
#define OUTCH 256
#define BK    32                     // k-halfs per stage
#define RSTR  40                     // smem row stride in halfs (80B, conflict-free)
#define STAGES 4
#define A_STG (128 * RSTR)           // halfs per A stage
#define B_STG (128 * RSTR)
#define DYN_SMEM ((STAGES * (A_STG + B_STG)) * 2)   // 81920 bytes

// Scratch (__device__ globals per allocation-free rule)
__device__ __half g_X  [B_ * N2_ * INCH];    // fp16 concat input
__device__ __half g_Y1 [B_ * N2_ * OUTCH];   // fp16 layer-1 output
__device__ __half g_W1h[OUTCH * INCH];       // [n][k] fp16
__device__ __half g_W2h[OUTCH * OUTCH];      // [n][k] fp16
__device__ int4   g_idx[B_ * N2_];           // per-query knn indices
__device__ float4 g_wt [B_ * N2_];           // per-query interp weights

// ---------------------------------------------------------------------------
// Kernel 0: transpose W -> [n][k] fp16
// ---------------------------------------------------------------------------
__global__ void prep_weights(const float* __restrict__ W1,
                             const float* __restrict__ W2)
{
    const int t = blockIdx.x * 256 + threadIdx.x;
    for (int i = t; i < INCH * OUTCH; i += gridDim.x * 256) {
        int k = i / OUTCH, n = i % OUTCH;
        g_W1h[n * INCH + k] = __float2half_rn(W1[i]);
    }
    for (int i = t; i < OUTCH * OUTCH; i += gridDim.x * 256) {
        int k = i / OUTCH, n = i % OUTCH;
        g_W2h[n * OUTCH + k] = __float2half_rn(W2[i]);
    }
}

// ---------------------------------------------------------------------------
// Kernel 1a: KNN selection, thread-per-query.
// All lanes scan the SAME point each step -> SMEM broadcast reads.
// Per-thread top-3 behind a rarely-taken branch (warp skips insert body
// whenever no lane needs it). Exact fp32 compares, strict-< (earliest index
// wins ties) == reference top_k tie policy.
// ---------------------------------------------------------------------------
__global__ __launch_bounds__(128) void knn_select(
    const float* __restrict__ xyz1, const float* __restrict__ xyz2)
{
    __shared__ float4 sp[N1_];
    const int b   = blockIdx.y;
    const int tid = threadIdx.x;

    const float* x1 = xyz1 + (size_t)b * N1_ * 3;
    for (int p = tid; p < N1_; p += 128) {
        float x = x1[3*p], y = x1[3*p+1], z = x1[3*p+2];
        sp[p] = make_float4(x, y, z, x*x + y*y + z*z);
    }
    __syncthreads();

    const int q   = blockIdx.x * 128 + tid;
    const int row = b * N2_ + q;

    const float qx = xyz2[row*3+0];
    const float qy = xyz2[row*3+1];
    const float qz = xyz2[row*3+2];
    const float q2 = qx*qx + qy*qy + qz*qz;
    const float ax = -2.f*qx, ay = -2.f*qy, az = -2.f*qz;

    float t0 = 3.4e38f, t1 = 3.4e38f, t2 = 3.4e38f;
    int   i0 = 0, i1 = 0, i2 = 0;

    #pragma unroll 4
    for (int i = 0; i < N1_; ++i) {
        float4 p = sp[i];
        float d = fmaf(ax, p.x, fmaf(ay, p.y, fmaf(az, p.z, p.w)));
        if (d < t2) {                       // warp-skipped ~81% of steps
            if (d < t1) {
                t2 = t1; i2 = i1;
                if (d < t0) { t1 = t0; i1 = i0; t0 = d; i0 = i; }
                else        { t1 = d;  i1 = i; }
            } else { t2 = d; i2 = i; }
        }
    }

    float d0 = fmaxf(t0 + q2, 1e-10f);
    float d1 = fmaxf(t1 + q2, 1e-10f);
    float d2 = fmaxf(t2 + q2, 1e-10f);
    float w0 = 1.f / (d0 + 1e-8f);
    float w1 = 1.f / (d1 + 1e-8f);
    float w2 = 1.f / (d2 + 1e-8f);
    float inv = 1.f / (w0 + w1 + w2);

    g_idx[row] = make_int4(i0, i1, i2, 0);
    g_wt [row] = make_float4(w0 * inv, w1 * inv, w2 * inv, 0.f);
}

// ---------------------------------------------------------------------------
// Kernel 1b: gather + interpolate + concat -> g_X (fp16). Warp per query,
// lanes over channels (fully coalesced 16B accesses).
// ---------------------------------------------------------------------------
__global__ __launch_bounds__(256) void interp_concat(
    const float* __restrict__ pts1, const float* __restrict__ pts2)
{
    const int b    = blockIdx.y;
    const int lane = threadIdx.x & 31;
    const int q    = blockIdx.x * 8 + (threadIdx.x >> 5);
    const int row  = b * N2_ + q;

    const int4   iv = g_idx[row];
    const float4 wv = g_wt [row];

    const float* p0f = pts1 + (size_t)(b * N1_ + iv.x) * C1_;
    const float* p1f = pts1 + (size_t)(b * N1_ + iv.y) * C1_;
    const float* p2f = pts1 + (size_t)(b * N1_ + iv.z) * C1_;
    __half* xr = g_X + (size_t)row * INCH;

    const int c8 = lane * 8;
    {
        float4 a0 = *(const float4*)(p0f + c8);
        float4 b0 = *(const float4*)(p1f + c8);
        float4 c0 = *(const float4*)(p2f + c8);
        float4 a1 = *(const float4*)(p0f + c8 + 4);
        float4 b1 = *(const float4*)(p1f + c8 + 4);
        float4 c1 = *(const float4*)(p2f + c8 + 4);
        __half2 h[4];
        h[0] = __floats2half2_rn(wv.x*a0.x + wv.y*b0.x + wv.z*c0.x,
                                 wv.x*a0.y + wv.y*b0.y + wv.z*c0.y);
        h[1] = __floats2half2_rn(wv.x*a0.z + wv.y*b0.z + wv.z*c0.z,
                                 wv.x*a0.w + wv.y*b0.w + wv.z*c0.w);
        h[2] = __floats2half2_rn(wv.x*a1.x + wv.y*b1.x + wv.z*c1.x,
                                 wv.x*a1.y + wv.y*b1.y + wv.z*c1.y);
        h[3] = __floats2half2_rn(wv.x*a1.z + wv.y*b1.z + wv.z*c1.z,
                                 wv.x*a1.w + wv.y*b1.w + wv.z*c1.w);
        *(uint4*)(xr + c8) = *(uint4*)h;
    }
    {
        const float* pq = pts2 + (size_t)row * C2_;
        float4 v = *(const float4*)(pq + lane * 4);
        __half2 h[2];
        h[0] = __floats2half2_rn(v.x, v.y);
        h[1] = __floats2half2_rn(v.z, v.w);
        *(uint2*)(xr + C1_ + lane * 4) = *(uint2*)h;
    }
}

// ---------------------------------------------------------------------------
// fp16 GEMM (unchanged from R7): 128x128 tile, BK=32, 4-stage cp.async,
// ldmatrix A frags, register double-buffered fragments, mma.m16n8k16,
// fused BN+ReLU. 8 warps (2m x 4n), warp 64x32.
// ---------------------------------------------------------------------------
__device__ __forceinline__ void cp16b(void* dst, const void* src) {
    uint32_t d = (uint32_t)__cvta_generic_to_shared(dst);
    asm volatile("cp.async.cg.shared.global [%0], [%1], 16;\n" :: "r"(d), "l"(src));
}
__device__ __forceinline__ void cp_commit() {
    asm volatile("cp.async.commit_group;\n");
}
__device__ __forceinline__ void cp_wait2() {
    asm volatile("cp.async.wait_group 2;\n");
}
__device__ __forceinline__ void ldsm_x4(uint32_t& r0, uint32_t& r1,
                                        uint32_t& r2, uint32_t& r3, uint32_t addr) {
    asm volatile("ldmatrix.sync.aligned.m8n8.x4.shared.b16 {%0,%1,%2,%3}, [%4];\n"
                 : "=r"(r0), "=r"(r1), "=r"(r2), "=r"(r3) : "r"(addr));
}
__device__ __forceinline__ void mma_f16(float c[4], const uint32_t a[4],
                                        uint32_t b0, uint32_t b1) {
    asm volatile(
        "mma.sync.aligned.m16n8k16.row.col.f32.f16.f16.f32 "
        "{%0,%1,%2,%3}, {%4,%5,%6,%7}, {%8,%9}, {%0,%1,%2,%3};"
        : "+f"(c[0]), "+f"(c[1]), "+f"(c[2]), "+f"(c[3])
        : "r"(a[0]), "r"(a[1]), "r"(a[2]), "r"(a[3]), "r"(b0), "r"(b1));
}

template<int K, bool HALF_OUT>
__device__ __forceinline__ void gemm_body(
    const __half* __restrict__ A, const __half* __restrict__ Wp,
    const float* __restrict__ bias, const float* __restrict__ gamma,
    const float* __restrict__ beta, const float* __restrict__ rmean,
    const float* __restrict__ rvar, void* __restrict__ Cout)
{
    extern __shared__ __half sm[];
    __half* sA = sm;
    __half* sB = sm + STAGES * A_STG;

    const int tid  = threadIdx.x;
    const int lane = tid & 31;
    const int warp = tid >> 5;
    const int wm   = warp & 1;
    const int wn   = warp >> 1;
    const int m0   = blockIdx.y * 128;
    const int n0   = blockIdx.x * 128;
    const int g4   = lane >> 2;
    const int c4   = lane & 3;

    const int rrow = tid >> 1;
    const int hofs = (tid & 1) * 16;

    const __half* Agp = A  + (size_t)(m0 + rrow) * K + hofs;
    const __half* Bgp = Wp + (size_t)(n0 + rrow) * K + hofs;
    __half* sAme = sA + rrow * RSTR + hofs;
    __half* sBme = sB + rrow * RSTR + hofs;

    constexpr int NK = K / BK;

    float acc[4][4][4];
    #pragma unroll
    for (int i = 0; i < 4; ++i)
        #pragma unroll
        for (int j = 0; j < 4; ++j)
            #pragma unroll
            for (int r = 0; r < 4; ++r) acc[i][j][r] = 0.f;

    #pragma unroll
    for (int p = 0; p < STAGES - 1; ++p) {
        if (p < NK) {
            cp16b(sAme + p * A_STG,     Agp + p * BK);
            cp16b(sAme + p * A_STG + 8, Agp + p * BK + 8);
            cp16b(sBme + p * B_STG,     Bgp + p * BK);
            cp16b(sBme + p * B_STG + 8, Bgp + p * BK + 8);
        }
        cp_commit();
    }
    cp_wait2();
    __syncthreads();

    const int a_row  = lane & 15;
    const int a_koff = (lane >= 16) ? 8 : 0;

    uint32_t curA[4][4], nxtA[4][4];
    uint32_t curB[4][2], nxtB[4][2];

    auto load_frags = [&](int stage, int kk, uint32_t fa[4][4], uint32_t fb[4][2]) {
        const __half* stA = sA + stage * A_STG;
        const __half* stB = sB + stage * B_STG;
        #pragma unroll
        for (int i = 0; i < 4; ++i) {
            const int r = wm * 64 + i * 16 + a_row;
            uint32_t addr = (uint32_t)__cvta_generic_to_shared(
                stA + r * RSTR + kk * 16 + a_koff);
            ldsm_x4(fa[i][0], fa[i][1], fa[i][2], fa[i][3], addr);
        }
        #pragma unroll
        for (int j = 0; j < 4; ++j) {
            const int cc = wn * 32 + j * 8 + g4;
            const __half* bp = stB + cc * RSTR + kk * 16 + 2 * c4;
            fb[j][0] = *(const uint32_t*)bp;
            fb[j][1] = *(const uint32_t*)(bp + 8);
        }
    };

    load_frags(0, 0, curA, curB);

    for (int kt = 0; kt < NK; ++kt) {
        const int stage = kt & (STAGES - 1);
        const int nxtkt = kt + STAGES - 1;
        if (nxtkt < NK) {
            const int st = nxtkt & (STAGES - 1);
            cp16b(sAme + st * A_STG,     Agp + nxtkt * BK);
            cp16b(sAme + st * A_STG + 8, Agp + nxtkt * BK + 8);
            cp16b(sBme + st * B_STG,     Bgp + nxtkt * BK);
            cp16b(sBme + st * B_STG + 8, Bgp + nxtkt * BK + 8);
        }
        cp_commit();
        cp_wait2();

        load_frags(stage, 1, nxtA, nxtB);
        #pragma unroll
        for (int i = 0; i < 4; ++i)
            #pragma unroll
            for (int j = 0; j < 4; ++j)
                mma_f16(acc[i][j], curA[i], curB[j][0], curB[j][1]);

        if (kt + 1 < NK)
            load_frags((kt + 1) & (STAGES - 1), 0, curA, curB);
        #pragma unroll
        for (int i = 0; i < 4; ++i)
            #pragma unroll
            for (int j = 0; j < 4; ++j)
                mma_f16(acc[i][j], nxtA[i], nxtB[j][0], nxtB[j][1]);

        __syncthreads();
    }

    float sc[4][2], sh[4][2];
    #pragma unroll
    for (int j = 0; j < 4; ++j) {
        #pragma unroll
        for (int e = 0; e < 2; ++e) {
            const int col = n0 + wn * 32 + j * 8 + 2 * c4 + e;
            const float s = gamma[col] * rsqrtf(rvar[col] + 1e-5f);
            sc[j][e] = s;
            sh[j][e] = (bias[col] - rmean[col]) * s + beta[col];
        }
    }
    #pragma unroll
    for (int i = 0; i < 4; ++i) {
        const int r0 = m0 + wm * 64 + i * 16 + g4;
        #pragma unroll
        for (int j = 0; j < 4; ++j) {
            const int cb = n0 + wn * 32 + j * 8 + 2 * c4;
            float v0 = fmaxf(acc[i][j][0] * sc[j][0] + sh[j][0], 0.f);
            float v1 = fmaxf(acc[i][j][1] * sc[j][1] + sh[j][1], 0.f);
            float v2 = fmaxf(acc[i][j][2] * sc[j][0] + sh[j][0], 0.f);
            float v3 = fmaxf(acc[i][j][3] * sc[j][1] + sh[j][1], 0.f);
            if (HALF_OUT) {
                __half* C = (__half*)Cout;
                *(__half2*)(C + (size_t)r0 * OUTCH + cb)       = __floats2half2_rn(v0, v1);
                *(__half2*)(C + (size_t)(r0 + 8) * OUTCH + cb) = __floats2half2_rn(v2, v3);
            } else {
                float* C = (float*)Cout;
                *(float2*)(C + (size_t)r0 * OUTCH + cb)       = make_float2(v0, v1);
                *(float2*)(C + (size_t)(r0 + 8) * OUTCH + cb) = make_float2(v2, v3);
            }
        }
    }
}

__global__ __launch_bounds__(256, 2) void gemm1_f16(
    const float* __restrict__ bias, const float* __restrict__ gamma,
    const float* __restrict__ beta, const float* __restrict__ rmean,
    const float* __restrict__ rvar)
{
    gemm_body<INCH, true>(g_X, g_W1h, bias, gamma, beta, rmean, rvar, g_Y1);
}

__global__ __launch_bounds__(256, 2) void gemm2_f16(
    const float* __restrict__ bias, const float* __restrict__ gamma,
    const float* __restrict__ beta, const float* __restrict__ rmean,
    const float* __restrict__ rvar, float* __restrict__ C)
{
    gemm_body<OUTCH, false>(g_Y1, g_W2h, bias, gamma, beta, rmean, rvar, C);
}

// ---------------------------------------------------------------------------
extern "C" void kernel_launch(void* const* d_in, const int* in_sizes, int n_in,
                              void* d_out, int out_size)
{
    const float* xyz1 = (const float*)d_in[0];
    const float* xyz2 = (const float*)d_in[1];
    const float* pts1 = (const float*)d_in[2];
    const float* pts2 = (const float*)d_in[3];
    const float* W1   = (const float*)d_in[4];
    const float* b1   = (const float*)d_in[5];
    const float* g1   = (const float*)d_in[6];
    const float* be1  = (const float*)d_in[7];
    const float* rm1  = (const float*)d_in[8];
    const float* rv1  = (const float*)d_in[9];
    const float* W2   = (const float*)d_in[10];
    const float* b2   = (const float*)d_in[11];
    const float* g2   = (const float*)d_in[12];
    const float* be2  = (const float*)d_in[13];
    const float* rm2  = (const float*)d_in[14];
    const float* rv2  = (const float*)d_in[15];
    float* out = (float*)d_out;

    static bool attr_set = false;
    if (!attr_set) {
        cudaFuncSetAttribute(gemm1_f16,
            cudaFuncAttributeMaxDynamicSharedMemorySize, DYN_SMEM);
        cudaFuncSetAttribute(gemm2_f16,
            cudaFuncAttributeMaxDynamicSharedMemorySize, DYN_SMEM);
        attr_set = true;
    }

    prep_weights<<<64, 256>>>(W1, W2);
    knn_select<<<dim3(N2_ / 128, B_), 128>>>(xyz1, xyz2);
    interp_concat<<<dim3(N2_ / 8, B_), 256>>>(pts1, pts2);
    gemm1_f16<<<dim3(OUTCH / 128, (B_ * N2_) / 128), 256, DYN_SMEM>>>(b1, g1, be1, rm1, rv1);
    gemm2_f16<<<dim3(OUTCH / 128, (B_ * N2_) / 128), 256, DYN_SMEM>>>(b2, g2, be2, rm2, rv2, out);
}

// round 9
// speedup vs baseline: 1.0998x; 1.0998x over previous
#include <cuda_runtime.h>
#include <cuda_fp16.h>
#include <cstdint>

#define B_    4
#define N1_   2048
#define N2_   8192
#define C1_   256
#define C2_   128
#define INCH  384
#define OUTCH 256
#define BK    32                     // k-halfs per stage
#define RSTR  40                     // smem row stride in halfs (80B, conflict-free)
#define STAGES 4
#define A_STG (128 * RSTR)           // halfs per A stage
#define B_STG (128 * RSTR)
#define DYN_SMEM ((STAGES * (A_STG + B_STG)) * 2)   // 81920 bytes

#define QB     64                    // queries per knn block
#define NSPLIT 4
#define SPTS   (N1_ / NSPLIT)        // 512 points per split

// Scratch (__device__ globals per allocation-free rule)
__device__ __half g_X  [B_ * N2_ * INCH];    // fp16 concat input
__device__ __half g_Y1 [B_ * N2_ * OUTCH];   // fp16 layer-1 output
__device__ __half g_W1h[OUTCH * INCH];       // [n][k] fp16
__device__ __half g_W2h[OUTCH * OUTCH];      // [n][k] fp16
__device__ int4   g_idx[B_ * N2_];           // per-query knn indices
__device__ float4 g_wt [B_ * N2_];           // per-query interp weights

// ---------------------------------------------------------------------------
// Kernel 0: transpose W -> [n][k] fp16
// ---------------------------------------------------------------------------
__global__ void prep_weights(const float* __restrict__ W1,
                             const float* __restrict__ W2)
{
    const int t = blockIdx.x * 256 + threadIdx.x;
    for (int i = t; i < INCH * OUTCH; i += gridDim.x * 256) {
        int k = i / OUTCH, n = i % OUTCH;
        g_W1h[n * INCH + k] = __float2half_rn(W1[i]);
    }
    for (int i = t; i < OUTCH * OUTCH; i += gridDim.x * 256) {
        int k = i / OUTCH, n = i % OUTCH;
        g_W2h[n * OUTCH + k] = __float2half_rn(W2[i]);
    }
}

// ---------------------------------------------------------------------------
// Kernel 1a: KNN selection, thread-per-query x split-K over points.
// Block: 256 threads = 64 queries x 4 splits of 512 points.
// All lanes of a warp share one split -> sp[i] reads are SMEM broadcasts.
// Ascending-index processing + strict-< insert == reference tie policy.
// Exact fp32 d' = |p|^2 - 2 q.p everywhere; merge of split top-3s is exact.
// ---------------------------------------------------------------------------
__global__ __launch_bounds__(256) void knn_select(
    const float* __restrict__ xyz1, const float* __restrict__ xyz2)
{
    __shared__ float4 sp[N1_];                 // 32 KB
    __shared__ float  sd[NSPLIT][QB][3];
    __shared__ int    si[NSPLIT][QB][3];

    const int b    = blockIdx.y;
    const int tid  = threadIdx.x;
    const int qi   = tid & (QB - 1);           // query within block
    const int spl  = tid >> 6;                 // split 0..3

    const float* x1 = xyz1 + (size_t)b * N1_ * 3;
    for (int p = tid; p < N1_; p += 256) {
        float x = x1[3*p], y = x1[3*p+1], z = x1[3*p+2];
        sp[p] = make_float4(x, y, z, x*x + y*y + z*z);
    }
    __syncthreads();

    const int q   = blockIdx.x * QB + qi;
    const int row = b * N2_ + q;

    const float qx = xyz2[row*3+0];
    const float qy = xyz2[row*3+1];
    const float qz = xyz2[row*3+2];
    const float q2 = qx*qx + qy*qy + qz*qz;
    const float ax = -2.f*qx, ay = -2.f*qy, az = -2.f*qz;

    float t0 = 3.4e38f, t1 = 3.4e38f, t2 = 3.4e38f;
    int   i0 = 0, i1 = 0, i2 = 0;

    const int base = spl * SPTS;
    #pragma unroll 4
    for (int i = 0; i < SPTS; ++i) {
        float4 p = sp[base + i];
        float d = fmaf(ax, p.x, fmaf(ay, p.y, fmaf(az, p.z, p.w)));
        if (d < t2) {
            if (d < t1) {
                t2 = t1; i2 = i1;
                if (d < t0) { t1 = t0; i1 = i0; t0 = d; i0 = base + i; }
                else        { t1 = d;  i1 = base + i; }
            } else { t2 = d; i2 = base + i; }
        }
    }

    sd[spl][qi][0] = t0; sd[spl][qi][1] = t1; sd[spl][qi][2] = t2;
    si[spl][qi][0] = i0; si[spl][qi][1] = i1; si[spl][qi][2] = i2;
    __syncthreads();

    // Merge 12 candidates (splits in ascending index order -> strict-< keeps
    // earliest index on exact ties, matching the per-split insert policy).
    if (tid < QB) {
        float m0 = 3.4e38f, m1 = 3.4e38f, m2 = 3.4e38f;
        int   j0 = 0, j1 = 0, j2 = 0;
        #pragma unroll
        for (int s = 0; s < NSPLIT; ++s) {
            #pragma unroll
            for (int r = 0; r < 3; ++r) {
                float d = sd[s][tid][r];
                int   ii = si[s][tid][r];
                if (d < m2) {
                    if (d < m1) {
                        m2 = m1; j2 = j1;
                        if (d < m0) { m1 = m0; j1 = j0; m0 = d; j0 = ii; }
                        else        { m1 = d;  j1 = ii; }
                    } else { m2 = d; j2 = ii; }
                }
            }
        }
        float d0 = fmaxf(m0 + q2, 1e-10f);
        float d1 = fmaxf(m1 + q2, 1e-10f);
        float d2 = fmaxf(m2 + q2, 1e-10f);
        float w0 = 1.f / (d0 + 1e-8f);
        float w1 = 1.f / (d1 + 1e-8f);
        float w2 = 1.f / (d2 + 1e-8f);
        float inv = 1.f / (w0 + w1 + w2);
        g_idx[row] = make_int4(j0, j1, j2, 0);
        g_wt [row] = make_float4(w0 * inv, w1 * inv, w2 * inv, 0.f);
    }
}

// ---------------------------------------------------------------------------
// Kernel 1b: gather + interpolate + concat -> g_X (fp16). Warp per query,
// lanes over channels (fully coalesced 16B accesses).
// ---------------------------------------------------------------------------
__global__ __launch_bounds__(256) void interp_concat(
    const float* __restrict__ pts1, const float* __restrict__ pts2)
{
    const int b    = blockIdx.y;
    const int lane = threadIdx.x & 31;
    const int q    = blockIdx.x * 8 + (threadIdx.x >> 5);
    const int row  = b * N2_ + q;

    const int4   iv = g_idx[row];
    const float4 wv = g_wt [row];

    const float* p0f = pts1 + (size_t)(b * N1_ + iv.x) * C1_;
    const float* p1f = pts1 + (size_t)(b * N1_ + iv.y) * C1_;
    const float* p2f = pts1 + (size_t)(b * N1_ + iv.z) * C1_;
    __half* xr = g_X + (size_t)row * INCH;

    const int c8 = lane * 8;
    {
        float4 a0 = *(const float4*)(p0f + c8);
        float4 b0 = *(const float4*)(p1f + c8);
        float4 c0 = *(const float4*)(p2f + c8);
        float4 a1 = *(const float4*)(p0f + c8 + 4);
        float4 b1 = *(const float4*)(p1f + c8 + 4);
        float4 c1 = *(const float4*)(p2f + c8 + 4);
        __half2 h[4];
        h[0] = __floats2half2_rn(wv.x*a0.x + wv.y*b0.x + wv.z*c0.x,
                                 wv.x*a0.y + wv.y*b0.y + wv.z*c0.y);
        h[1] = __floats2half2_rn(wv.x*a0.z + wv.y*b0.z + wv.z*c0.z,
                                 wv.x*a0.w + wv.y*b0.w + wv.z*c0.w);
        h[2] = __floats2half2_rn(wv.x*a1.x + wv.y*b1.x + wv.z*c1.x,
                                 wv.x*a1.y + wv.y*b1.y + wv.z*c1.y);
        h[3] = __floats2half2_rn(wv.x*a1.z + wv.y*b1.z + wv.z*c1.z,
                                 wv.x*a1.w + wv.y*b1.w + wv.z*c1.w);
        *(uint4*)(xr + c8) = *(uint4*)h;
    }
    {
        const float* pq = pts2 + (size_t)row * C2_;
        float4 v = *(const float4*)(pq + lane * 4);
        __half2 h[2];
        h[0] = __floats2half2_rn(v.x, v.y);
        h[1] = __floats2half2_rn(v.z, v.w);
        *(uint2*)(xr + C1_ + lane * 4) = *(uint2*)h;
    }
}

// ---------------------------------------------------------------------------
// fp16 GEMM (frozen from R7): 128x128 tile, BK=32, 4-stage cp.async,
// ldmatrix A frags, register double-buffered fragments, mma.m16n8k16,
// fused BN+ReLU. 8 warps (2m x 4n), warp 64x32.
// ---------------------------------------------------------------------------
__device__ __forceinline__ void cp16b(void* dst, const void* src) {
    uint32_t d = (uint32_t)__cvta_generic_to_shared(dst);
    asm volatile("cp.async.cg.shared.global [%0], [%1], 16;\n" :: "r"(d), "l"(src));
}
__device__ __forceinline__ void cp_commit() {
    asm volatile("cp.async.commit_group;\n");
}
__device__ __forceinline__ void cp_wait2() {
    asm volatile("cp.async.wait_group 2;\n");
}
__device__ __forceinline__ void ldsm_x4(uint32_t& r0, uint32_t& r1,
                                        uint32_t& r2, uint32_t& r3, uint32_t addr) {
    asm volatile("ldmatrix.sync.aligned.m8n8.x4.shared.b16 {%0,%1,%2,%3}, [%4];\n"
                 : "=r"(r0), "=r"(r1), "=r"(r2), "=r"(r3) : "r"(addr));
}
__device__ __forceinline__ void mma_f16(float c[4], const uint32_t a[4],
                                        uint32_t b0, uint32_t b1) {
    asm volatile(
        "mma.sync.aligned.m16n8k16.row.col.f32.f16.f16.f32 "
        "{%0,%1,%2,%3}, {%4,%5,%6,%7}, {%8,%9}, {%0,%1,%2,%3};"
        : "+f"(c[0]), "+f"(c[1]), "+f"(c[2]), "+f"(c[3])
        : "r"(a[0]), "r"(a[1]), "r"(a[2]), "r"(a[3]), "r"(b0), "r"(b1));
}

template<int K, bool HALF_OUT>
__device__ __forceinline__ void gemm_body(
    const __half* __restrict__ A, const __half* __restrict__ Wp,
    const float* __restrict__ bias, const float* __restrict__ gamma,
    const float* __restrict__ beta, const float* __restrict__ rmean,
    const float* __restrict__ rvar, void* __restrict__ Cout)
{
    extern __shared__ __half sm[];
    __half* sA = sm;
    __half* sB = sm + STAGES * A_STG;

    const int tid  = threadIdx.x;
    const int lane = tid & 31;
    const int warp = tid >> 5;
    const int wm   = warp & 1;
    const int wn   = warp >> 1;
    const int m0   = blockIdx.y * 128;
    const int n0   = blockIdx.x * 128;
    const int g4   = lane >> 2;
    const int c4   = lane & 3;

    const int rrow = tid >> 1;
    const int hofs = (tid & 1) * 16;

    const __half* Agp = A  + (size_t)(m0 + rrow) * K + hofs;
    const __half* Bgp = Wp + (size_t)(n0 + rrow) * K + hofs;
    __half* sAme = sA + rrow * RSTR + hofs;
    __half* sBme = sB + rrow * RSTR + hofs;

    constexpr int NK = K / BK;

    float acc[4][4][4];
    #pragma unroll
    for (int i = 0; i < 4; ++i)
        #pragma unroll
        for (int j = 0; j < 4; ++j)
            #pragma unroll
            for (int r = 0; r < 4; ++r) acc[i][j][r] = 0.f;

    #pragma unroll
    for (int p = 0; p < STAGES - 1; ++p) {
        if (p < NK) {
            cp16b(sAme + p * A_STG,     Agp + p * BK);
            cp16b(sAme + p * A_STG + 8, Agp + p * BK + 8);
            cp16b(sBme + p * B_STG,     Bgp + p * BK);
            cp16b(sBme + p * B_STG + 8, Bgp + p * BK + 8);
        }
        cp_commit();
    }
    cp_wait2();
    __syncthreads();

    const int a_row  = lane & 15;
    const int a_koff = (lane >= 16) ? 8 : 0;

    uint32_t curA[4][4], nxtA[4][4];
    uint32_t curB[4][2], nxtB[4][2];

    auto load_frags = [&](int stage, int kk, uint32_t fa[4][4], uint32_t fb[4][2]) {
        const __half* stA = sA + stage * A_STG;
        const __half* stB = sB + stage * B_STG;
        #pragma unroll
        for (int i = 0; i < 4; ++i) {
            const int r = wm * 64 + i * 16 + a_row;
            uint32_t addr = (uint32_t)__cvta_generic_to_shared(
                stA + r * RSTR + kk * 16 + a_koff);
            ldsm_x4(fa[i][0], fa[i][1], fa[i][2], fa[i][3], addr);
        }
        #pragma unroll
        for (int j = 0; j < 4; ++j) {
            const int cc = wn * 32 + j * 8 + g4;
            const __half* bp = stB + cc * RSTR + kk * 16 + 2 * c4;
            fb[j][0] = *(const uint32_t*)bp;
            fb[j][1] = *(const uint32_t*)(bp + 8);
        }
    };

    load_frags(0, 0, curA, curB);

    for (int kt = 0; kt < NK; ++kt) {
        const int stage = kt & (STAGES - 1);
        const int nxtkt = kt + STAGES - 1;
        if (nxtkt < NK) {
            const int st = nxtkt & (STAGES - 1);
            cp16b(sAme + st * A_STG,     Agp + nxtkt * BK);
            cp16b(sAme + st * A_STG + 8, Agp + nxtkt * BK + 8);
            cp16b(sBme + st * B_STG,     Bgp + nxtkt * BK);
            cp16b(sBme + st * B_STG + 8, Bgp + nxtkt * BK + 8);
        }
        cp_commit();
        cp_wait2();

        load_frags(stage, 1, nxtA, nxtB);
        #pragma unroll
        for (int i = 0; i < 4; ++i)
            #pragma unroll
            for (int j = 0; j < 4; ++j)
                mma_f16(acc[i][j], curA[i], curB[j][0], curB[j][1]);

        if (kt + 1 < NK)
            load_frags((kt + 1) & (STAGES - 1), 0, curA, curB);
        #pragma unroll
        for (int i = 0; i < 4; ++i)
            #pragma unroll
            for (int j = 0; j < 4; ++j)
                mma_f16(acc[i][j], nxtA[i], nxtB[j][0], nxtB[j][1]);

        __syncthreads();
    }

    float sc[4][2], sh[4][2];
    #pragma unroll
    for (int j = 0; j < 4; ++j) {
        #pragma unroll
        for (int e = 0; e < 2; ++e) {
            const int col = n0 + wn * 32 + j * 8 + 2 * c4 + e;
            const float s = gamma[col] * rsqrtf(rvar[col] + 1e-5f);
            sc[j][e] = s;
            sh[j][e] = (bias[col] - rmean[col]) * s + beta[col];
        }
    }
    #pragma unroll
    for (int i = 0; i < 4; ++i) {
        const int r0 = m0 + wm * 64 + i * 16 + g4;
        #pragma unroll
        for (int j = 0; j < 4; ++j) {
            const int cb = n0 + wn * 32 + j * 8 + 2 * c4;
            float v0 = fmaxf(acc[i][j][0] * sc[j][0] + sh[j][0], 0.f);
            float v1 = fmaxf(acc[i][j][1] * sc[j][1] + sh[j][1], 0.f);
            float v2 = fmaxf(acc[i][j][2] * sc[j][0] + sh[j][0], 0.f);
            float v3 = fmaxf(acc[i][j][3] * sc[j][1] + sh[j][1], 0.f);
            if (HALF_OUT) {
                __half* C = (__half*)Cout;
                *(__half2*)(C + (size_t)r0 * OUTCH + cb)       = __floats2half2_rn(v0, v1);
                *(__half2*)(C + (size_t)(r0 + 8) * OUTCH + cb) = __floats2half2_rn(v2, v3);
            } else {
                float* C = (float*)Cout;
                *(float2*)(C + (size_t)r0 * OUTCH + cb)       = make_float2(v0, v1);
                *(float2*)(C + (size_t)(r0 + 8) * OUTCH + cb) = make_float2(v2, v3);
            }
        }
    }
}

__global__ __launch_bounds__(256, 2) void gemm1_f16(
    const float* __restrict__ bias, const float* __restrict__ gamma,
    const float* __restrict__ beta, const float* __restrict__ rmean,
    const float* __restrict__ rvar)
{
    gemm_body<INCH, true>(g_X, g_W1h, bias, gamma, beta, rmean, rvar, g_Y1);
}

__global__ __launch_bounds__(256, 2) void gemm2_f16(
    const float* __restrict__ bias, const float* __restrict__ gamma,
    const float* __restrict__ beta, const float* __restrict__ rmean,
    const float* __restrict__ rvar, float* __restrict__ C)
{
    gemm_body<OUTCH, false>(g_Y1, g_W2h, bias, gamma, beta, rmean, rvar, C);
}

// ---------------------------------------------------------------------------
extern "C" void kernel_launch(void* const* d_in, const int* in_sizes, int n_in,
                              void* d_out, int out_size)
{
    const float* xyz1 = (const float*)d_in[0];
    const float* xyz2 = (const float*)d_in[1];
    const float* pts1 = (const float*)d_in[2];
    const float* pts2 = (const float*)d_in[3];
    const float* W1   = (const float*)d_in[4];
    const float* b1   = (const float*)d_in[5];
    const float* g1   = (const float*)d_in[6];
    const float* be1  = (const float*)d_in[7];
    const float* rm1  = (const float*)d_in[8];
    const float* rv1  = (const float*)d_in[9];
    const float* W2   = (const float*)d_in[10];
    const float* b2   = (const float*)d_in[11];
    const float* g2   = (const float*)d_in[12];
    const float* be2  = (const float*)d_in[13];
    const float* rm2  = (const float*)d_in[14];
    const float* rv2  = (const float*)d_in[15];
    float* out = (float*)d_out;

    static bool attr_set = false;
    if (!attr_set) {
        cudaFuncSetAttribute(gemm1_f16,
            cudaFuncAttributeMaxDynamicSharedMemorySize, DYN_SMEM);
        cudaFuncSetAttribute(gemm2_f16,
            cudaFuncAttributeMaxDynamicSharedMemorySize, DYN_SMEM);
        attr_set = true;
    }

    prep_weights<<<64, 256>>>(W1, W2);
    knn_select<<<dim3(N2_ / QB, B_), 256>>>(xyz1, xyz2);
    interp_concat<<<dim3(N2_ / 8, B_), 256>>>(pts1, pts2);
    gemm1_f16<<<dim3(OUTCH / 128, (B_ * N2_) / 128), 256, DYN_SMEM>>>(b1, g1, be1, rm1, rv1);
    gemm2_f16<<<dim3(OUTCH / 128, (B_ * N2_) / 128), 256, DYN_SMEM>>>(b2, g2, be2, rm2, rv2, out);
}

// round 11
// speedup vs baseline: 1.2041x; 1.0948x over previous
#include <cuda_runtime.h>
#include <cuda_fp16.h>
#include <cstdint>

#define B_    4
#define N1_   2048
#define N2_   8192
#define C1_   256
#define C2_   128
#define INCH  384
#define OUTCH 256
#define BK    32                     // k-halfs per stage
#define RSTR  40                     // smem row stride in halfs (80B, conflict-free)
#define STAGES 4
#define A_STG (128 * RSTR)           // halfs per A stage
#define B_STG (128 * RSTR)
#define DYN_SMEM ((STAGES * (A_STG + B_STG)) * 2)   // 81920 bytes

// Scratch (__device__ globals per allocation-free rule)
__device__ __half g_X  [B_ * N2_ * INCH];    // fp16 concat input
__device__ __half g_Y1 [B_ * N2_ * OUTCH];   // fp16 layer-1 output
__device__ __half g_W1h[OUTCH * INCH];       // [n][k] fp16
__device__ __half g_W2h[OUTCH * OUTCH];      // [n][k] fp16

// ---------------------------------------------------------------------------
// Kernel 0: transpose W -> [n][k] fp16
// ---------------------------------------------------------------------------
__global__ void prep_weights(const float* __restrict__ W1,
                             const float* __restrict__ W2)
{
    const int t = blockIdx.x * 256 + threadIdx.x;
    for (int i = t; i < INCH * OUTCH; i += gridDim.x * 256) {
        int k = i / OUTCH, n = i % OUTCH;
        g_W1h[n * INCH + k] = __float2half_rn(W1[i]);
    }
    for (int i = t; i < OUTCH * OUTCH; i += gridDim.x * 256) {
        int k = i / OUTCH, n = i % OUTCH;
        g_W2h[n * OUTCH + k] = __float2half_rn(W2[i]);
    }
}

// ---------------------------------------------------------------------------
// Kernel 1 (R7, measured-good): KNN (K=3) + interp + concat -> g_X (fp16).
// Warp per query; per-lane top-2 + exact rare repair; vectorized stores.
// ---------------------------------------------------------------------------
__global__ __launch_bounds__(512) void knn_interp_kernel(
    const float* __restrict__ xyz1, const float* __restrict__ xyz2,
    const float* __restrict__ pts1, const float* __restrict__ pts2)
{
    __shared__ float4 sp[N1_];
    const int b   = blockIdx.y;
    const int tid = threadIdx.x;

    const float* x1 = xyz1 + (size_t)b * N1_ * 3;
    for (int p = tid; p < N1_; p += 512) {
        float x = x1[3*p], y = x1[3*p+1], z = x1[3*p+2];
        sp[p] = make_float4(x, y, z, x*x + y*y + z*z);
    }
    __syncthreads();

    const int lane = tid & 31;
    const int q    = blockIdx.x * 16 + (tid >> 5);
    const int row  = b * N2_ + q;

    const float qx = xyz2[row*3+0];
    const float qy = xyz2[row*3+1];
    const float qz = xyz2[row*3+2];
    const float q2 = qx*qx + qy*qy + qz*qz;
    const float ax = -2.f*qx, ay = -2.f*qy, az = -2.f*qz;

    float t0 = 3.4e38f, t1 = 3.4e38f;
    int   i0 = -1,      i1 = -1;

    #pragma unroll 8
    for (int i = lane; i < N1_; i += 32) {
        float4 p = sp[i];
        float d = fmaf(ax, p.x, fmaf(ay, p.y, fmaf(az, p.z, p.w)));
        bool p1 = d < t1;
        bool p0 = d < t0;
        float nt1 = p0 ? t0 : d;
        int   ni1 = p0 ? i0 : i;
        t1 = p1 ? nt1 : t1;  i1 = p1 ? ni1 : i1;
        t0 = p0 ? d   : t0;  i0 = p0 ? i   : i0;
    }

    int head = 0;
    bool win0 = false, win1 = false;
    float selD[3]; int selI[3];
    #pragma unroll
    for (int r = 0; r < 3; ++r) {
        float cd  = (head == 0) ? t0 : (head == 1) ? t1 : 3.4e38f;
        int   ci  = (head == 0) ? i0 : (head == 1) ? i1 : 0;
        float bestD = cd; int bestLane = lane;
        #pragma unroll
        for (int off = 16; off; off >>= 1) {
            float od = __shfl_xor_sync(0xffffffffu, bestD, off);
            int   ol = __shfl_xor_sync(0xffffffffu, bestLane, off);
            if (od < bestD || (od == bestD && ol < bestLane)) { bestD = od; bestLane = ol; }
        }
        selD[r] = bestD;
        selI[r] = __shfl_sync(0xffffffffu, ci, bestLane);
        if (lane == bestLane) {
            if (r == 0) win0 = true;
            if (r == 1) win1 = true;
            head++;
        }
    }

    unsigned need = __ballot_sync(0xffffffffu, win0 && win1);
    if (need) {
        const int L = __ffs(need) - 1;
        float d3 = 3.4e38f; int i3 = 0x7fffffff;
        if (lane == L) {
            for (int i = lane; i < N1_; i += 32) {
                if (i == i0 || i == i1) continue;
                float4 p = sp[i];
                float d = fmaf(ax, p.x, fmaf(ay, p.y, fmaf(az, p.z, p.w)));
                if (d < d3 || (d == d3 && i < i3)) { d3 = d; i3 = i; }
            }
        }
        d3 = __shfl_sync(0xffffffffu, d3, L);
        i3 = __shfl_sync(0xffffffffu, i3, L);
        if (d3 < selD[2] || (d3 == selD[2] && i3 < selI[2])) {
            selD[2] = d3; selI[2] = i3;
        }
    }

    float d0 = fmaxf(selD[0] + q2, 1e-10f);
    float d1 = fmaxf(selD[1] + q2, 1e-10f);
    float d2 = fmaxf(selD[2] + q2, 1e-10f);
    float w0 = 1.f / (d0 + 1e-8f);
    float w1 = 1.f / (d1 + 1e-8f);
    float w2 = 1.f / (d2 + 1e-8f);
    float inv = 1.f / (w0 + w1 + w2);
    w0 *= inv; w1 *= inv; w2 *= inv;

    const float* p0f = pts1 + (size_t)(b * N1_ + selI[0]) * C1_;
    const float* p1f = pts1 + (size_t)(b * N1_ + selI[1]) * C1_;
    const float* p2f = pts1 + (size_t)(b * N1_ + selI[2]) * C1_;
    __half* xr = g_X + (size_t)row * INCH;

    const int c8 = lane * 8;
    {
        float4 a0 = *(const float4*)(p0f + c8);
        float4 b0 = *(const float4*)(p1f + c8);
        float4 c0 = *(const float4*)(p2f + c8);
        float4 a1 = *(const float4*)(p0f + c8 + 4);
        float4 b1 = *(const float4*)(p1f + c8 + 4);
        float4 c1 = *(const float4*)(p2f + c8 + 4);
        __half2 h[4];
        h[0] = __floats2half2_rn(w0*a0.x + w1*b0.x + w2*c0.x,
                                 w0*a0.y + w1*b0.y + w2*c0.y);
        h[1] = __floats2half2_rn(w0*a0.z + w1*b0.z + w2*c0.z,
                                 w0*a0.w + w1*b0.w + w2*c0.w);
        h[2] = __floats2half2_rn(w0*a1.x + w1*b1.x + w2*c1.x,
                                 w0*a1.y + w1*b1.y + w2*c1.y);
        h[3] = __floats2half2_rn(w0*a1.z + w1*b1.z + w2*c1.z,
                                 w0*a1.w + w1*b1.w + w2*c1.w);
        *(uint4*)(xr + c8) = *(uint4*)h;
    }
    {
        const float* pq = pts2 + (size_t)row * C2_;
        float4 v = *(const float4*)(pq + lane * 4);
        __half2 h[2];
        h[0] = __floats2half2_rn(v.x, v.y);
        h[1] = __floats2half2_rn(v.z, v.w);
        *(uint2*)(xr + C1_ + lane * 4) = *(uint2*)h;
    }
}

// ---------------------------------------------------------------------------
// fp16 GEMM: 128x128 tile, BK=32, 4-stage cp.async with FULL 3-iteration
// lookahead (wait_group 3), ldmatrix for BOTH operands, mma.m16n8k16,
// fused BN+ReLU. 8 warps (2m x 4n), warp 64x32.
// ---------------------------------------------------------------------------
__device__ __forceinline__ void cp16b(void* dst, const void* src) {
    uint32_t d = (uint32_t)__cvta_generic_to_shared(dst);
    asm volatile("cp.async.cg.shared.global [%0], [%1], 16;\n" :: "r"(d), "l"(src));
}
__device__ __forceinline__ void cp_commit() {
    asm volatile("cp.async.commit_group;\n");
}
__device__ __forceinline__ void cp_wait3() {
    asm volatile("cp.async.wait_group 3;\n");
}
__device__ __forceinline__ void ldsm_x4(uint32_t& r0, uint32_t& r1,
                                        uint32_t& r2, uint32_t& r3, uint32_t addr) {
    asm volatile("ldmatrix.sync.aligned.m8n8.x4.shared.b16 {%0,%1,%2,%3}, [%4];\n"
                 : "=r"(r0), "=r"(r1), "=r"(r2), "=r"(r3) : "r"(addr));
}
__device__ __forceinline__ void mma_f16(float c[4], const uint32_t a[4],
                                        uint32_t b0, uint32_t b1) {
    asm volatile(
        "mma.sync.aligned.m16n8k16.row.col.f32.f16.f16.f32 "
        "{%0,%1,%2,%3}, {%4,%5,%6,%7}, {%8,%9}, {%0,%1,%2,%3};"
        : "+f"(c[0]), "+f"(c[1]), "+f"(c[2]), "+f"(c[3])
        : "r"(a[0]), "r"(a[1]), "r"(a[2]), "r"(a[3]), "r"(b0), "r"(b1));
}

template<int K, bool HALF_OUT>
__device__ __forceinline__ void gemm_body(
    const __half* __restrict__ A, const __half* __restrict__ Wp,
    const float* __restrict__ bias, const float* __restrict__ gamma,
    const float* __restrict__ beta, const float* __restrict__ rmean,
    const float* __restrict__ rvar, void* __restrict__ Cout)
{
    extern __shared__ __half sm[];
    __half* sA = sm;
    __half* sB = sm + STAGES * A_STG;

    const int tid  = threadIdx.x;
    const int lane = tid & 31;
    const int warp = tid >> 5;
    const int wm   = warp & 1;
    const int wn   = warp >> 1;
    const int m0   = blockIdx.y * 128;
    const int n0   = blockIdx.x * 128;
    const int g4   = lane >> 2;
    const int c4   = lane & 3;

    const int rrow = tid >> 1;
    const int hofs = (tid & 1) * 16;

    const __half* Agp = A  + (size_t)(m0 + rrow) * K + hofs;
    const __half* Bgp = Wp + (size_t)(n0 + rrow) * K + hofs;
    __half* sAme = sA + rrow * RSTR + hofs;
    __half* sBme = sB + rrow * RSTR + hofs;

    constexpr int NK = K / BK;

    float acc[4][4][4];
    #pragma unroll
    for (int i = 0; i < 4; ++i)
        #pragma unroll
        for (int j = 0; j < 4; ++j)
            #pragma unroll
            for (int r = 0; r < 4; ++r) acc[i][j][r] = 0.f;

    // Prologue: issue stages 0..2 (one commit group each)
    #pragma unroll
    for (int p = 0; p < STAGES - 1; ++p) {
        if (p < NK) {
            cp16b(sAme + p * A_STG,     Agp + p * BK);
            cp16b(sAme + p * A_STG + 8, Agp + p * BK + 8);
            cp16b(sBme + p * B_STG,     Bgp + p * BK);
            cp16b(sBme + p * B_STG + 8, Bgp + p * BK + 8);
        }
        cp_commit();
    }

    // ldmatrix lane addressing
    const int a_row  = lane & 15;
    const int a_koff = (lane >= 16) ? 8 : 0;
    const int b_row  = ((lane >> 4) & 1) * 8 + (lane & 7);   // n offset within 16
    const int b_koff = ((lane >> 3) & 1) * 8;                // k offset within 16

    for (int kt = 0; kt < NK; ++kt) {
        __syncthreads();                 // all warps done reading stage kt-1
        const int nxtkt = kt + STAGES - 1;
        if (nxtkt < NK) {
            const int st = nxtkt & (STAGES - 1);
            cp16b(sAme + st * A_STG,     Agp + nxtkt * BK);
            cp16b(sAme + st * A_STG + 8, Agp + nxtkt * BK + 8);
            cp16b(sBme + st * B_STG,     Bgp + nxtkt * BK);
            cp16b(sBme + st * B_STG + 8, Bgp + nxtkt * BK + 8);
        }
        cp_commit();
        cp_wait3();                      // stage kt resident; 3-iter lookahead

        const __half* stA = sA + (kt & (STAGES - 1)) * A_STG;
        const __half* stB = sB + (kt & (STAGES - 1)) * B_STG;

        #pragma unroll
        for (int kk = 0; kk < 2; ++kk) {
            uint32_t fa[4][4], fb[4][2];
            #pragma unroll
            for (int i = 0; i < 4; ++i) {
                const int r = wm * 64 + i * 16 + a_row;
                uint32_t addr = (uint32_t)__cvta_generic_to_shared(
                    stA + r * RSTR + kk * 16 + a_koff);
                ldsm_x4(fa[i][0], fa[i][1], fa[i][2], fa[i][3], addr);
            }
            #pragma unroll
            for (int jh = 0; jh < 2; ++jh) {
                const int nr = wn * 32 + jh * 16 + b_row;
                uint32_t addr = (uint32_t)__cvta_generic_to_shared(
                    stB + nr * RSTR + kk * 16 + b_koff);
                ldsm_x4(fb[2*jh][0], fb[2*jh][1], fb[2*jh+1][0], fb[2*jh+1][1], addr);
            }
            #pragma unroll
            for (int i = 0; i < 4; ++i)
                #pragma unroll
                for (int j = 0; j < 4; ++j)
                    mma_f16(acc[i][j], fa[i], fb[j][0], fb[j][1]);
        }
    }

    float sc[4][2], sh[4][2];
    #pragma unroll
    for (int j = 0; j < 4; ++j) {
        #pragma unroll
        for (int e = 0; e < 2; ++e) {
            const int col = n0 + wn * 32 + j * 8 + 2 * c4 + e;
            const float s = gamma[col] * rsqrtf(rvar[col] + 1e-5f);
            sc[j][e] = s;
            sh[j][e] = (bias[col] - rmean[col]) * s + beta[col];
        }
    }
    #pragma unroll
    for (int i = 0; i < 4; ++i) {
        const int r0 = m0 + wm * 64 + i * 16 + g4;
        #pragma unroll
        for (int j = 0; j < 4; ++j) {
            const int cb = n0 + wn * 32 + j * 8 + 2 * c4;
            float v0 = fmaxf(acc[i][j][0] * sc[j][0] + sh[j][0], 0.f);
            float v1 = fmaxf(acc[i][j][1] * sc[j][1] + sh[j][1], 0.f);
            float v2 = fmaxf(acc[i][j][2] * sc[j][0] + sh[j][0], 0.f);
            float v3 = fmaxf(acc[i][j][3] * sc[j][1] + sh[j][1], 0.f);
            if (HALF_OUT) {
                __half* C = (__half*)Cout;
                *(__half2*)(C + (size_t)r0 * OUTCH + cb)       = __floats2half2_rn(v0, v1);
                *(__half2*)(C + (size_t)(r0 + 8) * OUTCH + cb) = __floats2half2_rn(v2, v3);
            } else {
                float* C = (float*)Cout;
                *(float2*)(C + (size_t)r0 * OUTCH + cb)       = make_float2(v0, v1);
                *(float2*)(C + (size_t)(r0 + 8) * OUTCH + cb) = make_float2(v2, v3);
            }
        }
    }
}

__global__ __launch_bounds__(256, 2) void gemm1_f16(
    const float* __restrict__ bias, const float* __restrict__ gamma,
    const float* __restrict__ beta, const float* __restrict__ rmean,
    const float* __restrict__ rvar)
{
    gemm_body<INCH, true>(g_X, g_W1h, bias, gamma, beta, rmean, rvar, g_Y1);
}

__global__ __launch_bounds__(256, 2) void gemm2_f16(
    const float* __restrict__ bias, const float* __restrict__ gamma,
    const float* __restrict__ beta, const float* __restrict__ rmean,
    const float* __restrict__ rvar, float* __restrict__ C)
{
    gemm_body<OUTCH, false>(g_Y1, g_W2h, bias, gamma, beta, rmean, rvar, C);
}

// ---------------------------------------------------------------------------
extern "C" void kernel_launch(void* const* d_in, const int* in_sizes, int n_in,
                              void* d_out, int out_size)
{
    const float* xyz1 = (const float*)d_in[0];
    const float* xyz2 = (const float*)d_in[1];
    const float* pts1 = (const float*)d_in[2];
    const float* pts2 = (const float*)d_in[3];
    const float* W1   = (const float*)d_in[4];
    const float* b1   = (const float*)d_in[5];
    const float* g1   = (const float*)d_in[6];
    const float* be1  = (const float*)d_in[7];
    const float* rm1  = (const float*)d_in[8];
    const float* rv1  = (const float*)d_in[9];
    const float* W2   = (const float*)d_in[10];
    const float* b2   = (const float*)d_in[11];
    const float* g2   = (const float*)d_in[12];
    const float* be2  = (const float*)d_in[13];
    const float* rm2  = (const float*)d_in[14];
    const float* rv2  = (const float*)d_in[15];
    float* out = (float*)d_out;

    static bool attr_set = false;
    if (!attr_set) {
        cudaFuncSetAttribute(gemm1_f16,
            cudaFuncAttributeMaxDynamicSharedMemorySize, DYN_SMEM);
        cudaFuncSetAttribute(gemm2_f16,
            cudaFuncAttributeMaxDynamicSharedMemorySize, DYN_SMEM);
        attr_set = true;
    }

    prep_weights<<<64, 256>>>(W1, W2);
    knn_interp_kernel<<<dim3(N2_ / 16, B_), 512>>>(xyz1, xyz2, pts1, pts2);
    gemm1_f16<<<dim3(OUTCH / 128, (B_ * N2_) / 128), 256, DYN_SMEM>>>(b1, g1, be1, rm1, rv1);
    gemm2_f16<<<dim3(OUTCH / 128, (B_ * N2_) / 128), 256, DYN_SMEM>>>(b2, g2, be2, rm2, rv2, out);
}